// round 2
// baseline (speedup 1.0000x reference)
#include <cuda_runtime.h>
#include <math.h>

#define MAXN 8192
#define NKEY 128          // NUM_IMGS(8) * NUM_CLASSES(16)
#define NUM_CLASSES 16
#define PPT 8             // points per thread in sort kernel (8192/1024)

// ---- scratch (no allocations allowed) ----
// key-sorted SoA, packed: a = {cx, cy, inv(2*sigma^2), score}, v = {cos4t, sin4t}
__device__ float4 s_a[MAXN];
__device__ float2 s_v[MAXN];
__device__ int    s_key[MAXN];
__device__ int    g_offs[NKEY + 1];

// Kernel A: single block — precompute + counting sort (smem hist/scan/cursors)
__global__ __launch_bounds__(1024, 1)
void k_sort(const float* __restrict__ preds,
            const float* __restrict__ scores,
            const int*   __restrict__ labels,
            const int*   __restrict__ batch,
            float* __restrict__ out, int n) {
    __shared__ int hist[NKEY];
    __shared__ int offs[NKEY + 1];

    int t = threadIdx.x;
    if (t < NKEY) hist[t] = 0;
    if (t == 0) *out = 0.0f;
    __syncthreads();

    // per-point precompute, held in registers
    float cx[PPT], cy[PPT], iv[PPT], sc[PPT], vx[PPT], vy[PPT];
    int   ky[PPT];
    int cnt = 0;
    for (int i = t; i < n && cnt < PPT; i += 1024, ++cnt) {
        const float* p = preds + 5 * i;
        float w  = p[2], h = p[3], th = p[4];
        float scale = fminf(fmaxf(sqrtf(w * h), 16.0f), 800.0f);
        float sig = 2.0f * scale;                    // K_RADIUS = 2
        cx[cnt] = p[0]; cy[cnt] = p[1];
        iv[cnt] = 1.0f / (2.0f * sig * sig);
        float sn, cs;
        sincosf(4.0f * th, &sn, &cs);
        vx[cnt] = cs; vy[cnt] = sn;
        sc[cnt] = scores[i];                         // SCORE_ALPHA = 1
        int key = batch[i] * NUM_CLASSES + labels[i];
        ky[cnt] = key;
        atomicAdd(&hist[key], 1);
    }
    __syncthreads();

    // serial 128-bin exclusive scan (cheap)
    if (t == 0) {
        int acc = 0;
        #pragma unroll 4
        for (int k = 0; k < NKEY; ++k) { offs[k] = acc; acc += hist[k]; }
        offs[NKEY] = acc;
    }
    __syncthreads();
    if (t <= NKEY) g_offs[t] = offs[t];
    // reuse hist as scatter cursors
    if (t < NKEY) hist[t] = offs[t];
    __syncthreads();

    // scatter: packed vector stores
    for (int k = 0; k < cnt; ++k) {
        int p = atomicAdd(&hist[ky[k]], 1);
        s_a[p] = make_float4(cx[k], cy[k], iv[k], sc[k]);
        s_v[p] = make_float2(vx[k], vy[k]);
        s_key[p] = ky[k];
    }
}

// Kernel B: per-point group sweep + mean reduction
__global__ __launch_bounds__(128)
void k_main(float* __restrict__ out, int n, float inv_n) {
    int p = blockIdx.x * blockDim.x + threadIdx.x;
    float chaos = 0.0f;
    if (p < n) {
        float4 a = s_a[p];               // cx, cy, inv, score
        int key = s_key[p];
        int beg = g_offs[key], end = g_offs[key + 1];
        float den = 0.0f, nx = 0.0f, ny = 0.0f;
        for (int j = beg; j < end; ++j) {
            float4 b = s_a[j];
            float2 v = s_v[j];
            float dx = a.x - b.x;
            float dy = a.y - b.y;
            float wgt = __expf(-(dx * dx + dy * dy) * a.z) * b.w;
            den += wgt;
            nx  += wgt * v.x;
            ny  += wgt * v.y;
        }
        chaos = 1.0f - sqrtf(nx * nx + ny * ny) / den;
    }
    // block reduction (128 threads = 4 warps)
    __shared__ float red[4];
    float v = chaos;
    #pragma unroll
    for (int o = 16; o; o >>= 1) v += __shfl_down_sync(0xffffffffu, v, o);
    if ((threadIdx.x & 31) == 0) red[threadIdx.x >> 5] = v;
    __syncthreads();
    if (threadIdx.x < 4) {
        v = red[threadIdx.x];
        v += __shfl_down_sync(0xfu, v, 2);
        v += __shfl_down_sync(0xfu, v, 1);
        if (threadIdx.x == 0) atomicAdd(out, v * inv_n);   // LOSS_WEIGHT = 1
    }
}

extern "C" void kernel_launch(void* const* d_in, const int* in_sizes, int n_in,
                              void* d_out, int out_size) {
    const float* preds  = (const float*)d_in[0];
    const float* scores = (const float*)d_in[1];
    const int*   labels = (const int*)d_in[2];
    const int*   batch  = (const int*)d_in[3];
    float* out = (float*)d_out;
    int n = in_sizes[1];                 // pos_scores element count = N

    k_sort<<<1, 1024>>>(preds, scores, labels, batch, out, n);
    k_main<<<(n + 127) / 128, 128>>>(out, n, 1.0f / (float)n);
}

// round 3
// speedup vs baseline: 2.1813x; 2.1813x over previous
#include <cuda_runtime.h>
#include <math.h>

#define MAXN 8192
#define NKEY 128          // NUM_IMGS(8) * NUM_CLASSES(16)
#define NUM_CLASSES 16

// ---- scratch (no allocations allowed; all state self-resetting per call) ----
__device__ float4 g_ua[MAXN];          // unsorted packed {cx, cy, inv, score}
__device__ float2 g_uv[MAXN];          // unsorted {cos4t, sin4t}
__device__ int    g_ukey[MAXN];
__device__ float4 s_a[MAXN];           // key-sorted
__device__ float2 s_v[MAXN];
__device__ int    s_key[MAXN];
__device__ int    g_hist[NKEY];        // zero at load; re-zeroed by last block each call
__device__ int    g_offs[NKEY + 1];
__device__ int    g_cursor[NKEY];
__device__ unsigned int g_ticket;      // zero at load; self-reset each call

// K1: per-point precompute + histogram; LAST block does scan + state reset
__global__ void k_pre(const float* __restrict__ preds,
                      const float* __restrict__ scores,
                      const int*   __restrict__ labels,
                      const int*   __restrict__ batch,
                      float* __restrict__ out, int n, int nblocks) {
    int i = blockIdx.x * blockDim.x + threadIdx.x;
    if (i < n) {
        const float* p = preds + 5 * i;
        float cx = p[0], cy = p[1], w = p[2], h = p[3], th = p[4];
        float scale = fminf(fmaxf(sqrtf(w * h), 16.0f), 800.0f);
        float sig = 2.0f * scale;                     // K_RADIUS = 2
        float inv = 1.0f / (2.0f * sig * sig);
        float sn, cs;
        sincosf(4.0f * th, &sn, &cs);
        g_ua[i] = make_float4(cx, cy, inv, scores[i]); // SCORE_ALPHA = 1
        g_uv[i] = make_float2(cs, sn);
        int key = batch[i] * NUM_CLASSES + labels[i];
        g_ukey[i] = key;
        atomicAdd(&g_hist[key], 1);                    // no return -> RED
    }

    // last-block-does-scan (ticket pattern)
    __shared__ int is_last;
    __threadfence();
    if (threadIdx.x == 0) {
        unsigned t = atomicAdd(&g_ticket, 1u);
        is_last = (t == (unsigned)(nblocks - 1));
    }
    __syncthreads();
    if (is_last && threadIdx.x < 32) {
        int l = threadIdx.x;                           // lane handles bins 4l..4l+3
        int v0 = g_hist[4 * l], v1 = g_hist[4 * l + 1];
        int v2 = g_hist[4 * l + 2], v3 = g_hist[4 * l + 3];
        int s = v0 + v1 + v2 + v3;
        int incl = s;
        #pragma unroll
        for (int o = 1; o < 32; o <<= 1) {
            int x = __shfl_up_sync(0xffffffffu, incl, o);
            if (l >= o) incl += x;
        }
        int e = incl - s;                              // exclusive prefix
        g_offs[4 * l] = e;         g_cursor[4 * l] = e;
        g_offs[4 * l + 1] = e + v0; g_cursor[4 * l + 1] = e + v0;
        g_offs[4 * l + 2] = e + v0 + v1; g_cursor[4 * l + 2] = e + v0 + v1;
        g_offs[4 * l + 3] = e + v0 + v1 + v2; g_cursor[4 * l + 3] = e + v0 + v1 + v2;
        if (l == 31) g_offs[NKEY] = incl;
        // reset state for next call
        g_hist[4 * l] = 0; g_hist[4 * l + 1] = 0;
        g_hist[4 * l + 2] = 0; g_hist[4 * l + 3] = 0;
        if (l == 0) { *out = 0.0f; g_ticket = 0u; }
    }
}

// K2: scatter into key-sorted SoA (packed vector stores)
__global__ void k_scatter(int n) {
    int i = blockIdx.x * blockDim.x + threadIdx.x;
    if (i >= n) return;
    int key = g_ukey[i];
    int p = atomicAdd(&g_cursor[key], 1);
    s_a[p] = g_ua[i];
    s_v[p] = g_uv[i];
    s_key[p] = key;
}

// K3: warp-per-point group sweep + reduction
__global__ __launch_bounds__(256)
void k_main(float* __restrict__ out, int n, float inv_n) {
    int warp = (blockIdx.x * blockDim.x + threadIdx.x) >> 5;
    int lane = threadIdx.x & 31;
    float chaos = 0.0f;
    if (warp < n) {
        float4 a = s_a[warp];                 // cx, cy, inv, score
        int key = s_key[warp];
        int beg = g_offs[key], end = g_offs[key + 1];
        float den = 0.0f, nx = 0.0f, ny = 0.0f;
        for (int j = beg + lane; j < end; j += 32) {
            float4 b = s_a[j];
            float2 v = s_v[j];
            float dx = a.x - b.x;
            float dy = a.y - b.y;
            float wgt = __expf(-(dx * dx + dy * dy) * a.z) * b.w;
            den += wgt;
            nx  += wgt * v.x;
            ny  += wgt * v.y;
        }
        #pragma unroll
        for (int o = 16; o; o >>= 1) {
            den += __shfl_xor_sync(0xffffffffu, den, o);
            nx  += __shfl_xor_sync(0xffffffffu, nx, o);
            ny  += __shfl_xor_sync(0xffffffffu, ny, o);
        }
        if (lane == 0) chaos = 1.0f - sqrtf(nx * nx + ny * ny) / den;
    }
    // block reduce: lane0 of each of 8 warps holds a chaos value
    __shared__ float red[8];
    if ((threadIdx.x & 31) == 0) red[threadIdx.x >> 5] = chaos;
    __syncthreads();
    if (threadIdx.x < 8) {
        float v = red[threadIdx.x];
        v += __shfl_xor_sync(0xffu, v, 4);
        v += __shfl_xor_sync(0xffu, v, 2);
        v += __shfl_xor_sync(0xffu, v, 1);
        if (threadIdx.x == 0) atomicAdd(out, v * inv_n);   // LOSS_WEIGHT = 1
    }
}

extern "C" void kernel_launch(void* const* d_in, const int* in_sizes, int n_in,
                              void* d_out, int out_size) {
    const float* preds  = (const float*)d_in[0];
    const float* scores = (const float*)d_in[1];
    const int*   labels = (const int*)d_in[2];
    const int*   batch  = (const int*)d_in[3];
    float* out = (float*)d_out;
    int n = in_sizes[1];                 // pos_scores element count = N

    int nb = (n + 127) / 128;
    k_pre<<<nb, 128>>>(preds, scores, labels, batch, out, n, nb);
    k_scatter<<<nb, 128>>>(n);
    int warps = n;                        // one warp per point
    int mb = (warps * 32 + 255) / 256;
    k_main<<<mb, 256>>>(out, n, 1.0f / (float)n);
}